// round 5
// baseline (speedup 1.0000x reference)
#include <cuda_runtime.h>

#define NUM_ENT   14541
#define EMBED_D   200
#define D2        100
#define D2_HALF   50
#define BATCH     256
#define TILE_B    64
#define TILE_N    131          // 111 * 131 == 14541 exactly
#define N_TILES   111
#define B_TILES   4
#define THREADS   512
#define ENT_PITCH 131
#define OBJ_PITCH 64           // [d2][wg(8)][i(8)] layout, 16B-aligned rows
#define SMEM_ULL  (D2 * ENT_PITCH + D2 * OBJ_PITCH)   // 19500
#define SMEM_BYTES (SMEM_ULL * 8)                      // 156000

typedef unsigned long long ull;

__device__ float g_obj[BATCH * EMBED_D];

__global__ void obj_kernel(const float* __restrict__ ent,
                           const float* __restrict__ rel_e,
                           const int* __restrict__ sub,
                           const int* __restrict__ rel) {
    int idx = blockIdx.x * blockDim.x + threadIdx.x;
    if (idx < BATCH * EMBED_D) {
        int b = idx / EMBED_D;
        int d = idx - b * EMBED_D;
        g_obj[idx] = ent[sub[b] * EMBED_D + d] + rel_e[rel[b] * EMBED_D + d];
    }
}

// Packed diff (fma pipe, 1 op) then unpack halves (pair-aliased, no SASS movs).
__device__ __forceinline__ void diff2(ull o, ull e_neg, float& lo, float& hi) {
    asm("{\n\t"
        ".reg .b64 t;\n\t"
        "add.rn.f32x2 t, %2, %3;\n\t"
        "mov.b64 {%0, %1}, t;\n\t"
        "}"
        : "=f"(lo), "=f"(hi) : "l"(o), "l"(e_neg));
}

__global__ void __launch_bounds__(THREADS, 1)
transe_kernel(const float* __restrict__ ent, float* __restrict__ out) {
    extern __shared__ ull smem[];
    ull* ent_s = smem;                     // [D2][ENT_PITCH], pre-negated
    ull* obj_s = smem + D2 * ENT_PITCH;    // [D2][8 wg][8 i]

    const int tid = threadIdx.x;
    const int n0  = blockIdx.x * TILE_N;
    const int b0  = blockIdx.y * TILE_B;

    // ---- ent tile: pre-negated, transposed to [d2][n] packed f32x2 ----
    for (int idx = tid; idx < TILE_N * D2; idx += THREADS) {
        int n  = idx / D2;
        int d2 = idx - n * D2;
        ull v = *reinterpret_cast<const ull*>(ent + (n0 + n) * EMBED_D + 2 * d2);
        ent_s[d2 * ENT_PITCH + n] = v ^ 0x8000000080000000ULL;  // negate both halves
    }
    // ---- obj tile: [d2][wg][i] where b = wg + 8*i ----
    for (int idx = tid; idx < TILE_B * D2; idx += THREADS) {
        int b  = idx / D2;
        int d2 = idx - b * D2;
        obj_s[d2 * OBJ_PITCH + (b & 7) * 8 + (b >> 3)] =
            *reinterpret_cast<const ull*>(g_obj + (b0 + b) * EMBED_D + 2 * d2);
    }
    __syncthreads();

    const int tn   = tid & 31;
    const int wg   = (tid >> 5) & 7;
    const int half = tid >> 8;         // 0: d2 [0,50), 1: d2 [50,100)
    const int d2lo = half * D2_HALF;

    float accL[32], accH[32];
#pragma unroll
    for (int k = 0; k < 32; k++) { accL[k] = 0.f; accH[k] = 0.f; }

#pragma unroll 1
    for (int d2 = d2lo; d2 < d2lo + D2_HALF; d2++) {
        // o: 4x LDS.128 broadcast; e: 4x LDS.64 stride-1 conflict-free
        const ulonglong2* orow =
            reinterpret_cast<const ulonglong2*>(obj_s + d2 * OBJ_PITCH + wg * 8);
        ulonglong2 op[4];
#pragma unroll
        for (int q = 0; q < 4; q++) op[q] = orow[q];
        ull e[4];
#pragma unroll
        for (int j = 0; j < 4; j++) e[j] = ent_s[d2 * ENT_PITCH + tn + 32 * j];

        ull o[8];
#pragma unroll
        for (int q = 0; q < 4; q++) { o[2 * q] = op[q].x; o[2 * q + 1] = op[q].y; }

#pragma unroll
        for (int i = 0; i < 8; i++) {
#pragma unroll
            for (int j = 0; j < 4; j++) {
                int k = i * 4 + j;
                float lo, hi;
                diff2(o[i], e[j], lo, hi);
                accL[k] += fabsf(lo);   // FADD Racc, Racc, |Rlo|  (fma pipe)
                accH[k] += fabsf(hi);
            }
        }
    }

    // ---- strip: remaining 3 columns (n = 128..130), full D, threads 0..191 ----
    if (tid < TILE_B * 3) {
        int sb = tid / 3;
        int sn = 128 + (tid - sb * 3);
        float sacc = 0.f;
#pragma unroll 4
        for (int d2 = 0; d2 < D2; d2++) {
            float lo, hi;
            diff2(obj_s[d2 * OBJ_PITCH + (sb & 7) * 8 + (sb >> 3)],
                  ent_s[d2 * ENT_PITCH + sn], lo, hi);
            sacc += fabsf(lo);
            sacc += fabsf(hi);
        }
        out[(b0 + sb) * NUM_ENT + (n0 + sn)] =
            __fdividef(1.0f, 1.0f + __expf(sacc - 9.0f));
    }

    // ---- combine halves: upper writes partials, lower reduces + outputs ----
    __syncthreads();
    float* part = reinterpret_cast<float*>(smem);   // [64][256] floats = 64 KB
    const int t8 = tid & 255;

    if (half == 1) {
#pragma unroll
        for (int k = 0; k < 32; k++) {
            part[(2 * k) * 256 + t8]     = accL[k];
            part[(2 * k + 1) * 256 + t8] = accH[k];
        }
    }
    __syncthreads();

    if (half == 0) {
#pragma unroll
        for (int k = 0; k < 32; k++) {
            int i = k >> 2, j = k & 3;
            int b = b0 + wg + 8 * i;
            float dist = (accL[k] + part[(2 * k) * 256 + t8]) +
                         (accH[k] + part[(2 * k + 1) * 256 + t8]);
            out[b * NUM_ENT + (n0 + tn + 32 * j)] =
                __fdividef(1.0f, 1.0f + __expf(dist - 9.0f));
        }
    }
}

extern "C" void kernel_launch(void* const* d_in, const int* in_sizes, int n_in,
                              void* d_out, int out_size) {
    const float* ent   = (const float*)d_in[0];
    const float* rel_e = (const float*)d_in[1];
    const int*   sub   = (const int*)d_in[2];
    const int*   rel   = (const int*)d_in[3];
    float* out = (float*)d_out;

    cudaFuncSetAttribute(transe_kernel,
                         cudaFuncAttributeMaxDynamicSharedMemorySize, SMEM_BYTES);

    obj_kernel<<<(BATCH * EMBED_D + 255) / 256, 256>>>(ent, rel_e, sub, rel);
    transe_kernel<<<dim3(N_TILES, B_TILES), THREADS, SMEM_BYTES>>>(ent, out);
}